// round 15
// baseline (speedup 1.0000x reference)
#include <cuda_runtime.h>
#include <cuda_fp16.h>
#include <cstdint>

// ============================================================================
// Problem constants
// ============================================================================
#define NU 128         // MUL0
#define NV 32          // A
#define KTOT 4096      // NU*NV
#define MT 32          // nodes per block
#define NCHUNK1 16     // stage-1 chunks of K=256
#define NCHUNK2 64     // stage-2 chunks of K=64
#define THREADS 256    // stage1: 4 consumer + 4 producer warps; stage2: all-hands ring
#define PT 128         // producer thread count

// W1 in fragment-direct layout: flat index (((g64*4+rgrp)*2+nbk)*4+ks)*2+hl, 32 lanes x uint4
__device__ __align__(16) uint4 g_W1F[64 * 4 * 2 * 4 * 2 * 32];   // 2 MB
// W2 pre-transposed hi/lo (stage 2)
__device__ __align__(16) __half g_W2T_hi[NV * KTOT];
__device__ __align__(16) __half g_W2T_lo[NV * KTOT];

// ---- smem layout (bytes) ----
// RING region shared by: stage1 A ring (2 x 32KB), stage2 ring (4 x 16KB), psum tail
constexpr uint32_t OFF_RING = 1024;       // 65536 bytes
constexpr uint32_t OFF_S    = 66560;      // sT / aT fp32 [128u][33] = 16896
constexpr uint32_t OFF_ATTR = 83456;      // attr fp32 [32n][36] = 4608
constexpr uint32_t OFF_H    = 88064;      // h fp32 [32n][33] = 4224
constexpr uint32_t OFF_W3   = 92288;      // 4096
constexpr uint32_t OFF_B1   = 96384;      // 512
constexpr uint32_t OFF_B2   = 96896;      // 128
constexpr uint32_t OFF_B3   = 97024;      // 128
constexpr uint32_t OFF_W4   = 97152;      // 128
constexpr uint32_t OFF_B4   = 97280;      // 16
constexpr uint32_t SMEM_BYTES = 97296;    // ~95 KB -> 2 CTAs/SM

extern __shared__ char smem_raw[];

__device__ __forceinline__ uint32_t smem_u32(const void* p) {
    uint32_t a;
    asm("{ .reg .u64 t; cvta.to.shared.u64 t, %1; cvt.u32.u64 %0, t; }" : "=r"(a) : "l"(p));
    return a;
}
__device__ __forceinline__ uint32_t swz(uint32_t o) { return o ^ ((o >> 3) & 0x70); }
__device__ __forceinline__ float silu_f(float x) { return x / (1.0f + __expf(-x)); }

#define STS128(r0, r1, r2, r3, sa) \
    asm volatile("st.shared.v4.b32 [%0], {%1, %2, %3, %4};" \
                 :: "r"(sa), "r"(r0), "r"(r1), "r"(r2), "r"(r3) : "memory")

// named barriers: FULL_b = 1+b, EMPTY_b = 3+b, block join = 15 (all count 256)
#define BAR_SYNC_ID(id)   asm volatile("bar.sync %0, %1;"   :: "r"(id), "n"(THREADS) : "memory")
#define BAR_ARRIVE_ID(id) asm volatile("bar.arrive %0, %1;" :: "r"(id), "n"(THREADS) : "memory")
#define BARX() asm volatile("bar.sync 15, %0;" :: "n"(THREADS) : "memory")

#define CP_ASYNC16(dst, src) \
    asm volatile("cp.async.cg.shared.global [%0], [%1], 16;" :: "r"(dst), "l"(src))
#define CP_ASYNC_COMMIT() asm volatile("cp.async.commit_group;" ::: "memory")
#define CP_ASYNC_WAIT_GROUP(n) asm volatile("cp.async.wait_group %0;" :: "n"(n) : "memory")

__device__ __forceinline__ void ldsm4(uint32_t* r, uint32_t addr) {
    asm volatile("ldmatrix.sync.aligned.m8n8.x4.shared.b16 {%0,%1,%2,%3}, [%4];"
                 : "=r"(r[0]), "=r"(r[1]), "=r"(r[2]), "=r"(r[3]) : "r"(addr));
}
// main pass: fp16 operands, fp32 accumulators
__device__ __forceinline__ void mma_f32(float* c, const uint32_t* a,
                                        uint32_t b0, uint32_t b1) {
    asm volatile(
        "mma.sync.aligned.m16n8k16.row.col.f32.f16.f16.f32 "
        "{%0,%1,%2,%3}, {%4,%5,%6,%7}, {%8,%9}, {%0,%1,%2,%3};"
        : "+f"(c[0]), "+f"(c[1]), "+f"(c[2]), "+f"(c[3])
        : "r"(a[0]), "r"(a[1]), "r"(a[2]), "r"(a[3]), "r"(b0), "r"(b1));
}
// correction passes: fp16 operands, fp16 accumulators
__device__ __forceinline__ void mma_f16(uint32_t* c, const uint32_t* a,
                                        uint32_t b0, uint32_t b1) {
    asm volatile(
        "mma.sync.aligned.m16n8k16.row.col.f16.f16.f16.f16 "
        "{%0,%1}, {%2,%3,%4,%5}, {%6,%7}, {%0,%1};"
        : "+r"(c[0]), "+r"(c[1])
        : "r"(a[0]), "r"(a[1]), "r"(a[2]), "r"(a[3]), "r"(b0), "r"(b1));
}

// ============================================================================
// prep kernel: blocks [0,64) -> W1 fragment layout; blocks [64,128) -> W2T hi/lo
// ============================================================================
__global__ void __launch_bounds__(256) prep_all(const float* __restrict__ W1s,
                                                const float* __restrict__ W2) {
    const int t = threadIdx.x;
    const int b = blockIdx.x;
    if (b < 64) {
        __shared__ float tile[64][132];
        const int g = b;
#pragma unroll
        for (int it = 0; it < 8; ++it) {          // 2048 float4 slots
            int s = it * 256 + t;
            int r = s >> 5, q = s & 31;
            float4 v = *(const float4*)(W1s + (size_t)(g * 64 + r) * NU + q * 4);
            tile[r][q * 4 + 0] = v.x; tile[r][q * 4 + 1] = v.y;
            tile[r][q * 4 + 2] = v.z; tile[r][q * 4 + 3] = v.w;
        }
        __syncthreads();
        const int l = t & 31, s = t >> 5;
        const int hl = s & 1, ks = s >> 1;
#pragma unroll
        for (int rgrp = 0; rgrp < 4; ++rgrp)
#pragma unroll
            for (int nbk = 0; nbk < 2; ++nbk) {
                uint32_t w[4];
#pragma unroll
                for (int j = 0; j < 4; ++j) {
                    int n  = rgrp * 32 + nbk * 16 + ((j >> 1) << 3) + (l >> 2);
                    int kh = ks * 16 + ((j & 1) << 3) + ((l & 3) << 1);
                    float x0 = tile[kh][n]     * 0.125f;
                    float x1 = tile[kh + 1][n] * 0.125f;
                    __half2 h2 = __float22half2_rn(make_float2(x0, x1));
                    float2 hf = __half22float2(h2);
                    __half2 l2 = __float22half2_rn(make_float2(x0 - hf.x, x1 - hf.y));
                    w[j] = hl ? *reinterpret_cast<uint32_t*>(&l2)
                              : *reinterpret_cast<uint32_t*>(&h2);
                }
                size_t flat = ((((size_t)g * 4 + rgrp) * 2 + nbk) * 4 + ks) * 2 + hl;
                g_W1F[flat * 32 + l] = make_uint4(w[0], w[1], w[2], w[3]);
            }
    } else {
        __shared__ float tile[64][65];
        const int k0 = (b - 64) * 64;
#pragma unroll
        for (int it = 0; it < 2; ++it) {
            int s = it * 256 + t;
            int r = s >> 3, q = s & 7;
            float4 v = *(const float4*)(W2 + (size_t)(k0 + r) * NV + q * 4);
            tile[r][q * 4 + 0] = v.x; tile[r][q * 4 + 1] = v.y;
            tile[r][q * 4 + 2] = v.z; tile[r][q * 4 + 3] = v.w;
        }
        __syncthreads();
        const int w = t >> 3, kq = t & 7;
        uint32_t hb[4], lb[4];
#pragma unroll
        for (int q = 0; q < 4; ++q) {
            float x0 = tile[kq * 8 + 2 * q][w]     * 0.125f;
            float x1 = tile[kq * 8 + 2 * q + 1][w] * 0.125f;
            __half2 h2 = __float22half2_rn(make_float2(x0, x1));
            float2 hf = __half22float2(h2);
            __half2 l2 = __float22half2_rn(make_float2(x0 - hf.x, x1 - hf.y));
            hb[q] = *reinterpret_cast<uint32_t*>(&h2);
            lb[q] = *reinterpret_cast<uint32_t*>(&l2);
        }
        ((uint4*)(g_W2T_hi + (size_t)w * KTOT + k0))[kq] =
            make_uint4(hb[0], hb[1], hb[2], hb[3]);
        ((uint4*)(g_W2T_lo + (size_t)w * KTOT + k0))[kq] =
            make_uint4(lb[0], lb[1], lb[2], lb[3]);
    }
}

// ============================================================================
// main fused kernel
// ============================================================================
__global__ void __launch_bounds__(THREADS, 2)
eq_hmma(const float* __restrict__ node_vec,   // [N,480]
        const float* __restrict__ attr_g,     // [N,32]
        const float* __restrict__ b1s,        // [128]
        const float* __restrict__ b2,         // [32]
        const float* __restrict__ W3,         // [32,32]
        const float* __restrict__ b3,         // [32]
        const float* __restrict__ W4,         // [32]
        const float* __restrict__ b4,         // [1]
        float* __restrict__ out)              // [N]
{
    const int tid  = threadIdx.x;
    const int wid  = tid >> 5;
    const int lane = tid & 31;
    const int nb   = blockIdx.x * MT;
    const uint32_t sb = smem_u32(smem_raw);
    const bool producer = (wid >= 4);
    const int ptid = tid - 128;

    float* sT    = (float*)(smem_raw + OFF_S);     // [u][33]
    float* attrS = (float*)(smem_raw + OFF_ATTR);  // [n][36]
    float* hS    = (float*)(smem_raw + OFF_H);     // [n][33]
    float* psum  = (float*)(smem_raw + OFF_RING);  // tail reuse: [ksg][32m][32n]
    float* w3S   = (float*)(smem_raw + OFF_W3);
    float* b1S   = (float*)(smem_raw + OFF_B1);
    float* b2S   = (float*)(smem_raw + OFF_B2);
    float* b3S   = (float*)(smem_raw + OFF_B3);
    float* w4S   = (float*)(smem_raw + OFF_W4);
    float* b4S   = (float*)(smem_raw + OFF_B4);

    // stage-1 A ring: buf b (0/1) x sub (0..3) x hi/lo, 4KB each
    auto A1 = [&](int b, int sub, int hl) {
        return sb + OFF_RING + (uint32_t)(b * 32768 + sub * 8192 + hl * 4096);
    };

    // ---- load block inputs (all 256 threads) ----
#pragma unroll
    for (int j = 0; j < 4; ++j) {              // s -> transposed [u][33]
        int i = tid + j * THREADS;             // 1024 float4 slots (32n x 32c4)
        int n = i >> 5, c4 = i & 31;
        float4 v = *(const float4*)(node_vec + (size_t)(nb + n) * 480 + c4 * 4);
        sT[(c4 * 4 + 0) * 33 + n] = v.x;
        sT[(c4 * 4 + 1) * 33 + n] = v.y;
        sT[(c4 * 4 + 2) * 33 + n] = v.z;
        sT[(c4 * 4 + 3) * 33 + n] = v.w;
    }
    {                                          // attr -> [n][36]
        int n = tid >> 3, c4 = tid & 7;
        *(float4*)(attrS + n * 36 + c4 * 4) =
            *(const float4*)(attr_g + (size_t)(nb + n) * NV + c4 * 4);
    }
    ((float4*)w3S)[tid] = ((const float4*)W3)[tid];
    if (tid < 128) b1S[tid] = b1s[tid];
    if (tid < 32) { b2S[tid] = b2[tid]; b3S[tid] = b3[tid]; w4S[tid] = W4[tid]; }
    if (tid == 0) b4S[0] = b4[0];
    __syncthreads();

    // ldmatrix per-lane offsets
    const uint32_t rowA = (uint32_t)((((lane >> 3) & 1) << 3) + (lane & 7));
    const uint32_t colA = (uint32_t)((lane >> 4) << 4);
    const uint32_t rowB = (uint32_t)(((lane >> 4) << 3) + (lane & 7));
    const uint32_t colB = (uint32_t)(((lane >> 3) & 1) << 4);

    // ============================== STAGE 1 (K=256 chunks) ==============================
    if (producer) {
        for (int c = 0; c < NCHUNK1; ++c) {
            const int b = c & 1;
            if (c >= 2) BAR_SYNC_ID(3 + b);            // EMPTY
#pragma unroll
            for (int j = 0; j < 8; ++j) {              // sub = j>>1
                const int sub = j >> 1;
                int slot = ptid + (j & 1) * PT;        // 0..255
                int n = slot >> 3, kgs = slot & 7;
                int vbs = (kgs & 3) << 3;
                int u = c * 8 + sub * 2 + (kgs >> 2);
                float su = sT[u * 33 + n] * 0.125f;
                float4 a0 = *(const float4*)(attrS + n * 36 + vbs);
                float4 a1 = *(const float4*)(attrS + n * 36 + vbs + 4);
                float v[8] = {a0.x, a0.y, a0.z, a0.w, a1.x, a1.y, a1.z, a1.w};
                uint32_t hb[4], lb[4];
#pragma unroll
                for (int q = 0; q < 4; ++q) {
                    float x0 = su * v[2 * q], x1 = su * v[2 * q + 1];
                    __half2 h2 = __float22half2_rn(make_float2(x0, x1));
                    float2 hf = __half22float2(h2);
                    __half2 l2 = __float22half2_rn(make_float2(x0 - hf.x, x1 - hf.y));
                    hb[q] = *reinterpret_cast<uint32_t*>(&h2);
                    lb[q] = *reinterpret_cast<uint32_t*>(&l2);
                }
                uint32_t sw = swz((uint32_t)(n * 128 + (kgs << 4)));
                STS128(hb[0], hb[1], hb[2], hb[3], A1(b, sub, 0) + sw);
                STS128(lb[0], lb[1], lb[2], lb[3], A1(b, sub, 1) + sw);
            }
            BAR_ARRIVE_ID(1 + b);                      // FULL (A only)
        }
        BARX();   // consumers wrote aT into sT
    } else {
        // B fragments straight from global (fragment-direct layout)
        auto ldB = [&](uint4* dst, int g64, int ks4) { // dst[nbk*2+hl]
#pragma unroll
            for (int nbk = 0; nbk < 2; ++nbk)
#pragma unroll
                for (int hl = 0; hl < 2; ++hl) {
                    size_t flat = ((((size_t)g64 * 4 + wid) * 2 + nbk) * 4 + ks4) * 2 + hl;
                    dst[nbk * 2 + hl] = __ldg(&g_W1F[flat * 32 + lane]);
                }
        };

        float    accF[2][4][4];
        uint32_t accC[2][4][2];
#pragma unroll
        for (int a = 0; a < 2; ++a)
#pragma unroll
            for (int b = 0; b < 4; ++b) {
#pragma unroll
                for (int q = 0; q < 4; ++q) accF[a][b][q] = 0.0f;
                accC[a][b][0] = 0u; accC[a][b][1] = 0u;
            }

        uint4 bf[2][4];                                // double-buffered per ks step
        ldB(bf[0], 0, 0);                              // t = 0

        for (int c = 0; c < NCHUNK1; ++c) {
            const int b = c & 1;
            BAR_SYNC_ID(1 + b);                        // FULL: A ready
#pragma unroll
            for (int ks16 = 0; ks16 < 16; ++ks16) {
                const int cur = ks16 & 1, nxt = cur ^ 1;
                const int t = c * 16 + ks16;
                if (t + 1 < NCHUNK1 * 16) ldB(bf[nxt], (t + 1) >> 2, (t + 1) & 3);
                const int sub = ks16 >> 2, ks4 = ks16 & 3;
                const uint32_t aHt = A1(b, sub, 0), aLt = A1(b, sub, 1);
                uint32_t aH[2][4], aL[2][4];
#pragma unroll
                for (int mf = 0; mf < 2; ++mf) {
                    uint32_t off = swz((uint32_t)((mf * 16 + rowA) * 128 + ks4 * 32 + colA));
                    ldsm4(aH[mf], aHt + off);
                    ldsm4(aL[mf], aLt + off);
                }
                if (ks16 == 15) BAR_ARRIVE_ID(3 + b);  // EMPTY early (A fully read)
#pragma unroll
                for (int mf = 0; mf < 2; ++mf)
#pragma unroll
                    for (int nf = 0; nf < 4; ++nf) {
                        const int nbk = nf >> 1, p = nf & 1;
                        const uint4 BH = bf[cur][nbk * 2 + 0];
                        const uint4 BL = bf[cur][nbk * 2 + 1];
                        uint32_t h0 = p ? BH.z : BH.x, h1 = p ? BH.w : BH.y;
                        uint32_t l0 = p ? BL.z : BL.x, l1 = p ? BL.w : BL.y;
                        mma_f32(accF[mf][nf], aH[mf], h0, h1);
                        mma_f16(accC[mf][nf], aH[mf], l0, l1);
                        mma_f16(accC[mf][nf], aL[mf], h0, h1);
                    }
            }
        }
        // epilogue 1: silu(c + corr + b1) -> sT[w][node]
        const int n0 = wid * 32;
#pragma unroll
        for (int mf = 0; mf < 2; ++mf)
#pragma unroll
            for (int nf = 0; nf < 4; ++nf) {
                int m = mf * 16 + (lane >> 2);
                int w = n0 + nf * 8 + ((lane & 3) << 1);
                float* cc = accF[mf][nf];
                float2 p0 = __half22float2(*(__half2*)&accC[mf][nf][0]);
                float2 p1 = __half22float2(*(__half2*)&accC[mf][nf][1]);
                sT[w * 33 + m]           = silu_f(cc[0] + p0.x + b1S[w]);
                sT[(w + 1) * 33 + m]     = silu_f(cc[1] + p0.y + b1S[w + 1]);
                sT[w * 33 + m + 8]       = silu_f(cc[2] + p1.x + b1S[w]);
                sT[(w + 1) * 33 + m + 8] = silu_f(cc[3] + p1.y + b1S[w + 1]);
            }
        BARX();   // join with producers; sT (aT) ready
    }

    // ================== STAGE 2: all-hands, 4-buffer ring, 2-chunk lookahead ==================
    {
        const int n2  = tid >> 3, kg2 = tid & 7;
        const int u2d = kg2 >> 2, vb2 = (kg2 & 3) << 3;
        float attrR[8];
#pragma unroll
        for (int q = 0; q < 8; ++q) attrR[q] = attrS[n2 * 36 + vb2 + q];
        const uint32_t swA2 = swz((uint32_t)(n2 * 128 + (kg2 << 4)));

        auto A2h = [&](int b) { return sb + OFF_RING + (uint32_t)(b * 16384); };
        auto A2l = [&](int b) { return sb + OFF_RING + (uint32_t)(b * 16384 + 4096); };
        auto B2h = [&](int b) { return sb + OFF_RING + (uint32_t)(b * 16384 + 8192); };
        auto B2l = [&](int b) { return sb + OFF_RING + (uint32_t)(b * 16384 + 12288); };

        auto fill2 = [&](int c, int b) {
            const char* srcH = (const char*)g_W2T_hi + (size_t)(n2 * 512 + c * 8 + kg2) * 16;
            const char* srcL = (const char*)g_W2T_lo + (size_t)(n2 * 512 + c * 8 + kg2) * 16;
            CP_ASYNC16(B2h(b) + swA2, srcH);
            CP_ASYNC16(B2l(b) + swA2, srcL);
            float su = sT[((c << 1) + u2d) * 33 + n2] * 0.125f;
            uint32_t hb[4], lb[4];
#pragma unroll
            for (int q = 0; q < 4; ++q) {
                float x0 = su * attrR[2 * q], x1 = su * attrR[2 * q + 1];
                __half2 h2 = __float22half2_rn(make_float2(x0, x1));
                float2 hf = __half22float2(h2);
                __half2 l2 = __float22half2_rn(make_float2(x0 - hf.x, x1 - hf.y));
                hb[q] = *reinterpret_cast<uint32_t*>(&h2);
                lb[q] = *reinterpret_cast<uint32_t*>(&l2);
            }
            STS128(hb[0], hb[1], hb[2], hb[3], A2h(b) + swA2);
            STS128(lb[0], lb[1], lb[2], lb[3], A2l(b) + swA2);
        };

        const int mg  = wid >> 2;            // 0..1 (m half)
        const int ksg = wid & 3;             // 0..3 (k slice of 16)
        float    accF[4][4];
        uint32_t accC[4][2];
#pragma unroll
        for (int b = 0; b < 4; ++b) {
#pragma unroll
            for (int q = 0; q < 4; ++q) accF[b][q] = 0.0f;
            accC[b][0] = 0u; accC[b][1] = 0u;
        }

        fill2(0, 0); CP_ASYNC_COMMIT();
        fill2(1, 1); CP_ASYNC_COMMIT();

        for (int c = 0; c < NCHUNK2; ++c) {
            const int b = c & 3;
            if (c + 2 < NCHUNK2) fill2(c + 2, (c + 2) & 3);
            CP_ASYNC_COMMIT();                 // group c+2 (possibly empty)
            CP_ASYNC_WAIT_GROUP(2);            // group c complete
            __syncthreads();
            uint32_t aH[4], aL[4], bH[2][4], bL[2][4];
            {
                uint32_t off = swz((uint32_t)((mg * 16 + rowA) * 128 + ksg * 32 + colA));
                ldsm4(aH, A2h(b) + off);
                ldsm4(aL, A2l(b) + off);
            }
#pragma unroll
            for (int ngk = 0; ngk < 2; ++ngk) {
                uint32_t off = swz((uint32_t)((ngk * 16 + rowB) * 128 + ksg * 32 + colB));
                ldsm4(bH[ngk], B2h(b) + off);
                ldsm4(bL[ngk], B2l(b) + off);
            }
#pragma unroll
            for (int nf = 0; nf < 4; ++nf) {
                uint32_t h0 = bH[nf >> 1][(nf & 1) * 2], h1 = bH[nf >> 1][(nf & 1) * 2 + 1];
                uint32_t l0 = bL[nf >> 1][(nf & 1) * 2], l1 = bL[nf >> 1][(nf & 1) * 2 + 1];
                mma_f32(accF[nf], aH, h0, h1);
                mma_f16(accC[nf], aH, l0, l1);
                mma_f16(accC[nf], aL, h0, h1);
            }
        }
        __syncthreads();   // ring buffers dead; region free for psum

        // write k-partials (main + corrections) to psum
#pragma unroll
        for (int nf = 0; nf < 4; ++nf) {
            int m = mg * 16 + (lane >> 2);
            int w = nf * 8 + ((lane & 3) << 1);
            float* cc = accF[nf];
            float2 p0 = __half22float2(*(__half2*)&accC[nf][0]);
            float2 p1 = __half22float2(*(__half2*)&accC[nf][1]);
            psum[(ksg * 32 + m) * 32 + w]         = cc[0] + p0.x;
            psum[(ksg * 32 + m) * 32 + w + 1]     = cc[1] + p0.y;
            psum[(ksg * 32 + m + 8) * 32 + w]     = cc[2] + p1.x;
            psum[(ksg * 32 + m + 8) * 32 + w + 1] = cc[3] + p1.y;
        }
        __syncthreads();
    }

    // reduce 4 k-partials + bias -> hS (all 256 threads)
#pragma unroll
    for (int j = 0; j < 4; ++j) {
        int idx = tid + j * THREADS;           // [0, 1024)
        int m = idx >> 5, n = idx & 31;
        float h = psum[m * 32 + n] + psum[(32 + m) * 32 + n]
                + psum[(64 + m) * 32 + n] + psum[(96 + m) * 32 + n] + b2S[n];
        hS[m * 33 + n] = h;
    }
    __syncthreads();

    // ======================= stage 3/4: 8 threads per node =======================
    {
        const int node  = tid >> 3;            // [0,32)
        const int lane8 = tid & 7;
        const float inv32 = 0.17677669529663687f;  // 1/sqrt(32)
        float o = 0.0f;
#pragma unroll
        for (int j = 0; j < 4; ++j) {
            int w = lane8 + j * 8;
            float z = 0.0f;
#pragma unroll
            for (int k = 0; k < 32; ++k) z += hS[node * 33 + k] * w3S[k * 32 + w];
            z = z * inv32 + b3S[w];
            o += silu_f(z) * (w4S[w] * inv32);
        }
#pragma unroll
        for (int m = 1; m < 8; m <<= 1)
            o += __shfl_xor_sync(0xffffffff, o, m);
        if (lane8 == 0) out[nb + node] = o + b4S[0];
    }
}

// ============================================================================
extern "C" void kernel_launch(void* const* d_in, const int* in_sizes, int n_in,
                              void* d_out, int out_size) {
    const float* node_vec = (const float*)d_in[0];
    const float* attr     = (const float*)d_in[1];
    const float* W1s      = (const float*)d_in[2];
    const float* b1s      = (const float*)d_in[3];
    // d_in[4..7] = W1g, b1g, W1v1, W1v2 : dead in the reference
    const float* W2       = (const float*)d_in[8];
    const float* b2       = (const float*)d_in[9];
    const float* W3       = (const float*)d_in[10];
    const float* b3       = (const float*)d_in[11];
    const float* W4       = (const float*)d_in[12];
    const float* b4       = (const float*)d_in[13];
    float* out = (float*)d_out;

    const int N = out_size;                    // 8192

    prep_all<<<128, 256>>>(W1s, W2);

    cudaFuncSetAttribute(eq_hmma, cudaFuncAttributeMaxDynamicSharedMemorySize,
                         (int)SMEM_BYTES);
    eq_hmma<<<N / MT, THREADS, SMEM_BYTES>>>(node_vec, attr, b1s, b2, W3, b3, W4, b4, out);
}

// round 16
// speedup vs baseline: 1.0463x; 1.0463x over previous
#include <cuda_runtime.h>
#include <cuda_fp16.h>
#include <cstdint>

// ============================================================================
// Problem constants
// ============================================================================
#define NU 128         // MUL0
#define NV 32          // A
#define KTOT 4096      // NU*NV
#define MT 32          // nodes per block
#define NCHUNK1 32     // stage-1 chunks of K=128
#define NCHUNK2 32     // stage-2 chunks of K=128
#define THREADS 256    // stage1: 4 consumer + 4 producer warps; stage2: all-hands
#define PT 128         // producer thread count

// W1 in fragment-direct layout: flat index (((g64*4+rgrp)*2+nbk)*4+ks)*2+hl, 32 lanes x uint4
__device__ __align__(16) uint4 g_W1F[64 * 4 * 2 * 4 * 2 * 32];   // 2 MB
// W2 pre-transposed hi/lo (stage 2)
__device__ __align__(16) __half g_W2T_hi[NV * KTOT];
__device__ __align__(16) __half g_W2T_lo[NV * KTOT];

// ---- smem layout (bytes) ----
// RING region shared by: stage1 A ring (2 x 16KB), stage2 ring (2 x 32KB), psum tail
constexpr uint32_t OFF_RING = 1024;       // 65536 bytes
constexpr uint32_t OFF_S    = 66560;      // sT / aT fp32 [128u][33] = 16896
constexpr uint32_t OFF_ATTR = 83456;      // attr fp32 [32n][36] = 4608
constexpr uint32_t OFF_H    = 88064;      // h fp32 [32n][33] = 4224
constexpr uint32_t OFF_W3   = 92288;      // 4096
constexpr uint32_t OFF_B1   = 96384;      // 512
constexpr uint32_t OFF_B2   = 96896;      // 128
constexpr uint32_t OFF_B3   = 97024;      // 128
constexpr uint32_t OFF_W4   = 97152;      // 128
constexpr uint32_t OFF_B4   = 97280;      // 16
constexpr uint32_t SMEM_BYTES = 97296;    // ~95 KB -> 2 CTAs/SM

extern __shared__ char smem_raw[];

__device__ __forceinline__ uint32_t smem_u32(const void* p) {
    uint32_t a;
    asm("{ .reg .u64 t; cvta.to.shared.u64 t, %1; cvt.u32.u64 %0, t; }" : "=r"(a) : "l"(p));
    return a;
}
__device__ __forceinline__ uint32_t swz(uint32_t o) { return o ^ ((o >> 3) & 0x70); }
__device__ __forceinline__ float silu_f(float x) { return x / (1.0f + __expf(-x)); }

#define STS128(r0, r1, r2, r3, sa) \
    asm volatile("st.shared.v4.b32 [%0], {%1, %2, %3, %4};" \
                 :: "r"(sa), "r"(r0), "r"(r1), "r"(r2), "r"(r3) : "memory")

// named barriers: FULL_b = 1+b, EMPTY_b = 3+b, block join = 15 (all count 256)
#define BAR_SYNC_ID(id)   asm volatile("bar.sync %0, %1;"   :: "r"(id), "n"(THREADS) : "memory")
#define BAR_ARRIVE_ID(id) asm volatile("bar.arrive %0, %1;" :: "r"(id), "n"(THREADS) : "memory")
#define BARX() asm volatile("bar.sync 15, %0;" :: "n"(THREADS) : "memory")

#define CP_ASYNC16(dst, src) \
    asm volatile("cp.async.cg.shared.global [%0], [%1], 16;" :: "r"(dst), "l"(src))
#define CP_ASYNC_COMMIT() asm volatile("cp.async.commit_group;" ::: "memory")
#define CP_ASYNC_WAIT_GROUP(n) asm volatile("cp.async.wait_group %0;" :: "n"(n) : "memory")

__device__ __forceinline__ void ldsm4(uint32_t* r, uint32_t addr) {
    asm volatile("ldmatrix.sync.aligned.m8n8.x4.shared.b16 {%0,%1,%2,%3}, [%4];"
                 : "=r"(r[0]), "=r"(r[1]), "=r"(r[2]), "=r"(r[3]) : "r"(addr));
}
// main pass: fp16 operands, fp32 accumulators
__device__ __forceinline__ void mma_f32(float* c, const uint32_t* a,
                                        uint32_t b0, uint32_t b1) {
    asm volatile(
        "mma.sync.aligned.m16n8k16.row.col.f32.f16.f16.f32 "
        "{%0,%1,%2,%3}, {%4,%5,%6,%7}, {%8,%9}, {%0,%1,%2,%3};"
        : "+f"(c[0]), "+f"(c[1]), "+f"(c[2]), "+f"(c[3])
        : "r"(a[0]), "r"(a[1]), "r"(a[2]), "r"(a[3]), "r"(b0), "r"(b1));
}
// correction passes: fp16 operands, fp16 accumulators
__device__ __forceinline__ void mma_f16(uint32_t* c, const uint32_t* a,
                                        uint32_t b0, uint32_t b1) {
    asm volatile(
        "mma.sync.aligned.m16n8k16.row.col.f16.f16.f16.f16 "
        "{%0,%1}, {%2,%3,%4,%5}, {%6,%7}, {%0,%1};"
        : "+r"(c[0]), "+r"(c[1])
        : "r"(a[0]), "r"(a[1]), "r"(a[2]), "r"(a[3]), "r"(b0), "r"(b1));
}

// ============================================================================
// prep kernel: blocks [0,64) -> W1 fragment layout; blocks [64,128) -> W2T hi/lo
// ============================================================================
__global__ void __launch_bounds__(256) prep_all(const float* __restrict__ W1s,
                                                const float* __restrict__ W2) {
    const int t = threadIdx.x;
    const int b = blockIdx.x;
    if (b < 64) {
        __shared__ float tile[64][132];
        const int g = b;
#pragma unroll
        for (int it = 0; it < 8; ++it) {          // 2048 float4 slots
            int s = it * 256 + t;
            int r = s >> 5, q = s & 31;
            float4 v = *(const float4*)(W1s + (size_t)(g * 64 + r) * NU + q * 4);
            tile[r][q * 4 + 0] = v.x; tile[r][q * 4 + 1] = v.y;
            tile[r][q * 4 + 2] = v.z; tile[r][q * 4 + 3] = v.w;
        }
        __syncthreads();
        const int l = t & 31, s = t >> 5;
        const int hl = s & 1, ks = s >> 1;
#pragma unroll
        for (int rgrp = 0; rgrp < 4; ++rgrp)
#pragma unroll
            for (int nbk = 0; nbk < 2; ++nbk) {
                uint32_t w[4];
#pragma unroll
                for (int j = 0; j < 4; ++j) {
                    int n  = rgrp * 32 + nbk * 16 + ((j >> 1) << 3) + (l >> 2);
                    int kh = ks * 16 + ((j & 1) << 3) + ((l & 3) << 1);
                    float x0 = tile[kh][n]     * 0.125f;
                    float x1 = tile[kh + 1][n] * 0.125f;
                    __half2 h2 = __float22half2_rn(make_float2(x0, x1));
                    float2 hf = __half22float2(h2);
                    __half2 l2 = __float22half2_rn(make_float2(x0 - hf.x, x1 - hf.y));
                    w[j] = hl ? *reinterpret_cast<uint32_t*>(&l2)
                              : *reinterpret_cast<uint32_t*>(&h2);
                }
                size_t flat = ((((size_t)g * 4 + rgrp) * 2 + nbk) * 4 + ks) * 2 + hl;
                g_W1F[flat * 32 + l] = make_uint4(w[0], w[1], w[2], w[3]);
            }
    } else {
        __shared__ float tile[64][65];
        const int k0 = (b - 64) * 64;
#pragma unroll
        for (int it = 0; it < 2; ++it) {
            int s = it * 256 + t;
            int r = s >> 3, q = s & 7;
            float4 v = *(const float4*)(W2 + (size_t)(k0 + r) * NV + q * 4);
            tile[r][q * 4 + 0] = v.x; tile[r][q * 4 + 1] = v.y;
            tile[r][q * 4 + 2] = v.z; tile[r][q * 4 + 3] = v.w;
        }
        __syncthreads();
        const int w = t >> 3, kq = t & 7;
        uint32_t hb[4], lb[4];
#pragma unroll
        for (int q = 0; q < 4; ++q) {
            float x0 = tile[kq * 8 + 2 * q][w]     * 0.125f;
            float x1 = tile[kq * 8 + 2 * q + 1][w] * 0.125f;
            __half2 h2 = __float22half2_rn(make_float2(x0, x1));
            float2 hf = __half22float2(h2);
            __half2 l2 = __float22half2_rn(make_float2(x0 - hf.x, x1 - hf.y));
            hb[q] = *reinterpret_cast<uint32_t*>(&h2);
            lb[q] = *reinterpret_cast<uint32_t*>(&l2);
        }
        ((uint4*)(g_W2T_hi + (size_t)w * KTOT + k0))[kq] =
            make_uint4(hb[0], hb[1], hb[2], hb[3]);
        ((uint4*)(g_W2T_lo + (size_t)w * KTOT + k0))[kq] =
            make_uint4(lb[0], lb[1], lb[2], lb[3]);
    }
}

// ============================================================================
// main fused kernel
// ============================================================================
__global__ void __launch_bounds__(THREADS, 2)
eq_hmma(const float* __restrict__ node_vec,   // [N,480]
        const float* __restrict__ attr_g,     // [N,32]
        const float* __restrict__ b1s,        // [128]
        const float* __restrict__ b2,         // [32]
        const float* __restrict__ W3,         // [32,32]
        const float* __restrict__ b3,         // [32]
        const float* __restrict__ W4,         // [32]
        const float* __restrict__ b4,         // [1]
        float* __restrict__ out)              // [N]
{
    const int tid  = threadIdx.x;
    const int wid  = tid >> 5;
    const int lane = tid & 31;
    const int nb   = blockIdx.x * MT;
    const uint32_t sb = smem_u32(smem_raw);
    const bool producer = (wid >= 4);
    const int ptid = tid - 128;

    float* sT    = (float*)(smem_raw + OFF_S);     // [u][33]
    float* attrS = (float*)(smem_raw + OFF_ATTR);  // [n][36]
    float* hS    = (float*)(smem_raw + OFF_H);     // [n][33]
    float* psum  = (float*)(smem_raw + OFF_RING);  // tail reuse: [ksg][32m][32n]
    float* w3S   = (float*)(smem_raw + OFF_W3);
    float* b1S   = (float*)(smem_raw + OFF_B1);
    float* b2S   = (float*)(smem_raw + OFF_B2);
    float* b3S   = (float*)(smem_raw + OFF_B3);
    float* w4S   = (float*)(smem_raw + OFF_W4);
    float* b4S   = (float*)(smem_raw + OFF_B4);

    // stage-1 A ring: buf b (0/1) x sub (0/1) x hi/lo, 4KB each  (R14 layout)
    auto A1 = [&](int b, int sub, int hl) {
        return sb + OFF_RING + (uint32_t)(b * 16384 + sub * 8192 + hl * 4096);
    };

    // ---- load block inputs (all 256 threads) ----
#pragma unroll
    for (int j = 0; j < 4; ++j) {              // s -> transposed [u][33]
        int i = tid + j * THREADS;             // 1024 float4 slots (32n x 32c4)
        int n = i >> 5, c4 = i & 31;
        float4 v = *(const float4*)(node_vec + (size_t)(nb + n) * 480 + c4 * 4);
        sT[(c4 * 4 + 0) * 33 + n] = v.x;
        sT[(c4 * 4 + 1) * 33 + n] = v.y;
        sT[(c4 * 4 + 2) * 33 + n] = v.z;
        sT[(c4 * 4 + 3) * 33 + n] = v.w;
    }
    {                                          // attr -> [n][36]
        int n = tid >> 3, c4 = tid & 7;
        *(float4*)(attrS + n * 36 + c4 * 4) =
            *(const float4*)(attr_g + (size_t)(nb + n) * NV + c4 * 4);
    }
    ((float4*)w3S)[tid] = ((const float4*)W3)[tid];
    if (tid < 128) b1S[tid] = b1s[tid];
    if (tid < 32) { b2S[tid] = b2[tid]; b3S[tid] = b3[tid]; w4S[tid] = W4[tid]; }
    if (tid == 0) b4S[0] = b4[0];
    __syncthreads();

    // ldmatrix per-lane offsets
    const uint32_t rowA = (uint32_t)((((lane >> 3) & 1) << 3) + (lane & 7));
    const uint32_t colA = (uint32_t)((lane >> 4) << 4);
    const uint32_t rowB = (uint32_t)(((lane >> 4) << 3) + (lane & 7));
    const uint32_t colB = (uint32_t)(((lane >> 3) & 1) << 4);

    // ============================== STAGE 1 (K=128 chunks, R14 verbatim) ==============================
    if (producer) {
        for (int c = 0; c < NCHUNK1; ++c) {
            const int b = c & 1;
            if (c >= 2) BAR_SYNC_ID(3 + b);            // EMPTY
#pragma unroll
            for (int j = 0; j < 4; ++j) {              // sub = j>>1
                const int sub = j >> 1;
                int slot = ptid + (j & 1) * PT;        // 0..255
                int n = slot >> 3, kgs = slot & 7;
                int vbs = (kgs & 3) << 3;
                int u = c * 4 + sub * 2 + (kgs >> 2);
                float su = sT[u * 33 + n] * 0.125f;
                float4 a0 = *(const float4*)(attrS + n * 36 + vbs);
                float4 a1 = *(const float4*)(attrS + n * 36 + vbs + 4);
                float v[8] = {a0.x, a0.y, a0.z, a0.w, a1.x, a1.y, a1.z, a1.w};
                uint32_t hb[4], lb[4];
#pragma unroll
                for (int q = 0; q < 4; ++q) {
                    float x0 = su * v[2 * q], x1 = su * v[2 * q + 1];
                    __half2 h2 = __float22half2_rn(make_float2(x0, x1));
                    float2 hf = __half22float2(h2);
                    __half2 l2 = __float22half2_rn(make_float2(x0 - hf.x, x1 - hf.y));
                    hb[q] = *reinterpret_cast<uint32_t*>(&h2);
                    lb[q] = *reinterpret_cast<uint32_t*>(&l2);
                }
                uint32_t sw = swz((uint32_t)(n * 128 + (kgs << 4)));
                STS128(hb[0], hb[1], hb[2], hb[3], A1(b, sub, 0) + sw);
                STS128(lb[0], lb[1], lb[2], lb[3], A1(b, sub, 1) + sw);
            }
            BAR_ARRIVE_ID(1 + b);                      // FULL (A only)
        }
        BARX();   // consumers wrote aT into sT
    } else {
        // B fragments straight from global (fragment-direct layout)
        auto ldB = [&](uint4* dst, int g64, int ks4) { // dst[nbk*2+hl]
#pragma unroll
            for (int nbk = 0; nbk < 2; ++nbk)
#pragma unroll
                for (int hl = 0; hl < 2; ++hl) {
                    size_t flat = ((((size_t)g64 * 4 + wid) * 2 + nbk) * 4 + ks4) * 2 + hl;
                    dst[nbk * 2 + hl] = __ldg(&g_W1F[flat * 32 + lane]);
                }
        };

        float    accF[2][4][4];
        uint32_t accC[2][4][2];
#pragma unroll
        for (int a = 0; a < 2; ++a)
#pragma unroll
            for (int b = 0; b < 4; ++b) {
#pragma unroll
                for (int q = 0; q < 4; ++q) accF[a][b][q] = 0.0f;
                accC[a][b][0] = 0u; accC[a][b][1] = 0u;
            }

        uint4 bf[2][4];                                // double-buffered per ks step
        ldB(bf[0], 0, 0);                              // t = 0

        for (int c = 0; c < NCHUNK1; ++c) {
            const int b = c & 1;
            BAR_SYNC_ID(1 + b);                        // FULL: A ready
#pragma unroll
            for (int ks8 = 0; ks8 < 8; ++ks8) {
                const int cur = ks8 & 1, nxt = cur ^ 1;
                const int t = c * 8 + ks8;
                if (t + 1 < NCHUNK1 * 8) ldB(bf[nxt], (t + 1) >> 2, (t + 1) & 3);
                const int sub = ks8 >> 2, ks4 = ks8 & 3;
                const uint32_t aHt = A1(b, sub, 0), aLt = A1(b, sub, 1);
                uint32_t aH[2][4], aL[2][4];
#pragma unroll
                for (int mf = 0; mf < 2; ++mf) {
                    uint32_t off = swz((uint32_t)((mf * 16 + rowA) * 128 + ks4 * 32 + colA));
                    ldsm4(aH[mf], aHt + off);
                    ldsm4(aL[mf], aLt + off);
                }
                if (ks8 == 7) BAR_ARRIVE_ID(3 + b);    // EMPTY early (A fully read)
#pragma unroll
                for (int mf = 0; mf < 2; ++mf)
#pragma unroll
                    for (int nf = 0; nf < 4; ++nf) {
                        const int nbk = nf >> 1, p = nf & 1;
                        const uint4 BH = bf[cur][nbk * 2 + 0];
                        const uint4 BL = bf[cur][nbk * 2 + 1];
                        uint32_t h0 = p ? BH.z : BH.x, h1 = p ? BH.w : BH.y;
                        uint32_t l0 = p ? BL.z : BL.x, l1 = p ? BL.w : BL.y;
                        mma_f32(accF[mf][nf], aH[mf], h0, h1);
                        mma_f16(accC[mf][nf], aH[mf], l0, l1);
                        mma_f16(accC[mf][nf], aL[mf], h0, h1);
                    }
            }
        }
        // epilogue 1: silu(c + corr + b1) -> sT[w][node]
        const int n0 = wid * 32;
#pragma unroll
        for (int mf = 0; mf < 2; ++mf)
#pragma unroll
            for (int nf = 0; nf < 4; ++nf) {
                int m = mf * 16 + (lane >> 2);
                int w = n0 + nf * 8 + ((lane & 3) << 1);
                float* cc = accF[mf][nf];
                float2 p0 = __half22float2(*(__half2*)&accC[mf][nf][0]);
                float2 p1 = __half22float2(*(__half2*)&accC[mf][nf][1]);
                sT[w * 33 + m]           = silu_f(cc[0] + p0.x + b1S[w]);
                sT[(w + 1) * 33 + m]     = silu_f(cc[1] + p0.y + b1S[w + 1]);
                sT[w * 33 + m + 8]       = silu_f(cc[2] + p1.x + b1S[w]);
                sT[(w + 1) * 33 + m + 8] = silu_f(cc[3] + p1.y + b1S[w + 1]);
            }
        BARX();   // join with producers; sT (aT) ready
    }

    // ========== STAGE 2: all-hands, K=128 chunks, 2 x 32KB buffers ==========
    {
        const int n2  = tid >> 3, kg2 = tid & 7;
        const int u2d = kg2 >> 2, vb2 = (kg2 & 3) << 3;
        float attrR[8];
#pragma unroll
        for (int q = 0; q < 8; ++q) attrR[q] = attrS[n2 * 36 + vb2 + q];
        const uint32_t swA2 = swz((uint32_t)(n2 * 128 + (kg2 << 4)));

        // buf b (0/1) x sub (0/1) x hi/lo: A first 16KB, B second 16KB
        auto A2 = [&](int b, int s, int hl) {
            return sb + OFF_RING + (uint32_t)(b * 32768 + s * 8192 + hl * 4096);
        };
        auto B2 = [&](int b, int s, int hl) {
            return sb + OFF_RING + (uint32_t)(b * 32768 + 16384 + s * 8192 + hl * 4096);
        };

        auto fill2 = [&](int c, int b) {
#pragma unroll
            for (int s = 0; s < 2; ++s) {
                const char* srcH = (const char*)g_W2T_hi +
                                   (size_t)(n2 * 512 + (c * 2 + s) * 8 + kg2) * 16;
                const char* srcL = (const char*)g_W2T_lo +
                                   (size_t)(n2 * 512 + (c * 2 + s) * 8 + kg2) * 16;
                CP_ASYNC16(B2(b, s, 0) + swA2, srcH);
                CP_ASYNC16(B2(b, s, 1) + swA2, srcL);
                float su = sT[(c * 4 + s * 2 + u2d) * 33 + n2] * 0.125f;
                uint32_t hb[4], lb[4];
#pragma unroll
                for (int q = 0; q < 4; ++q) {
                    float x0 = su * attrR[2 * q], x1 = su * attrR[2 * q + 1];
                    __half2 h2 = __float22half2_rn(make_float2(x0, x1));
                    float2 hf = __half22float2(h2);
                    __half2 l2 = __float22half2_rn(make_float2(x0 - hf.x, x1 - hf.y));
                    hb[q] = *reinterpret_cast<uint32_t*>(&h2);
                    lb[q] = *reinterpret_cast<uint32_t*>(&l2);
                }
                STS128(hb[0], hb[1], hb[2], hb[3], A2(b, s, 0) + swA2);
                STS128(lb[0], lb[1], lb[2], lb[3], A2(b, s, 1) + swA2);
            }
        };

        const int mg  = wid >> 2;            // 0..1 (m half)
        const int ksg = wid & 3;             // 0..3 (k slice of 16)
        float    accF[4][4];
        uint32_t accC[4][2];
#pragma unroll
        for (int b = 0; b < 4; ++b) {
#pragma unroll
            for (int q = 0; q < 4; ++q) accF[b][q] = 0.0f;
            accC[b][0] = 0u; accC[b][1] = 0u;
        }

        fill2(0, 0); CP_ASYNC_COMMIT();

        for (int c = 0; c < NCHUNK2; ++c) {
            const int b = c & 1;
            __syncthreads();                   // all reads of buf b^1 (chunk c-1) done
            if (c + 1 < NCHUNK2) fill2(c + 1, b ^ 1);
            CP_ASYNC_COMMIT();                 // group c+1 (possibly empty)
            CP_ASYNC_WAIT_GROUP(1);            // group c complete (committed last iter)
            __syncthreads();                   // fills of buf b visible to all
#pragma unroll
            for (int s = 0; s < 2; ++s) {
                uint32_t aH[4], aL[4], bH[2][4], bL[2][4];
                {
                    uint32_t off = swz((uint32_t)((mg * 16 + rowA) * 128 + ksg * 32 + colA));
                    ldsm4(aH, A2(b, s, 0) + off);
                    ldsm4(aL, A2(b, s, 1) + off);
                }
#pragma unroll
                for (int ngk = 0; ngk < 2; ++ngk) {
                    uint32_t off = swz((uint32_t)((ngk * 16 + rowB) * 128 + ksg * 32 + colB));
                    ldsm4(bH[ngk], B2(b, s, 0) + off);
                    ldsm4(bL[ngk], B2(b, s, 1) + off);
                }
#pragma unroll
                for (int nf = 0; nf < 4; ++nf) {
                    uint32_t h0 = bH[nf >> 1][(nf & 1) * 2], h1 = bH[nf >> 1][(nf & 1) * 2 + 1];
                    uint32_t l0 = bL[nf >> 1][(nf & 1) * 2], l1 = bL[nf >> 1][(nf & 1) * 2 + 1];
                    mma_f32(accF[nf], aH, h0, h1);
                    mma_f16(accC[nf], aH, l0, l1);
                    mma_f16(accC[nf], aL, h0, h1);
                }
            }
        }
        __syncthreads();   // ring buffers dead; region free for psum

        // write k-partials (main + corrections) to psum
#pragma unroll
        for (int nf = 0; nf < 4; ++nf) {
            int m = mg * 16 + (lane >> 2);
            int w = nf * 8 + ((lane & 3) << 1);
            float* cc = accF[nf];
            float2 p0 = __half22float2(*(__half2*)&accC[nf][0]);
            float2 p1 = __half22float2(*(__half2*)&accC[nf][1]);
            psum[(ksg * 32 + m) * 32 + w]         = cc[0] + p0.x;
            psum[(ksg * 32 + m) * 32 + w + 1]     = cc[1] + p0.y;
            psum[(ksg * 32 + m + 8) * 32 + w]     = cc[2] + p1.x;
            psum[(ksg * 32 + m + 8) * 32 + w + 1] = cc[3] + p1.y;
        }
        __syncthreads();
    }

    // reduce 4 k-partials + bias -> hS (all 256 threads)
#pragma unroll
    for (int j = 0; j < 4; ++j) {
        int idx = tid + j * THREADS;           // [0, 1024)
        int m = idx >> 5, n = idx & 31;
        float h = psum[m * 32 + n] + psum[(32 + m) * 32 + n]
                + psum[(64 + m) * 32 + n] + psum[(96 + m) * 32 + n] + b2S[n];
        hS[m * 33 + n] = h;
    }
    __syncthreads();

    // ======================= stage 3/4: 8 threads per node =======================
    {
        const int node  = tid >> 3;            // [0,32)
        const int lane8 = tid & 7;
        const float inv32 = 0.17677669529663687f;  // 1/sqrt(32)
        float o = 0.0f;
#pragma unroll
        for (int j = 0; j < 4; ++j) {
            int w = lane8 + j * 8;
            float z = 0.0f;
#pragma unroll
            for (int k = 0; k < 32; ++k) z += hS[node * 33 + k] * w3S[k * 32 + w];
            z = z * inv32 + b3S[w];
            o += silu_f(z) * (w4S[w] * inv32);
        }
#pragma unroll
        for (int m = 1; m < 8; m <<= 1)
            o += __shfl_xor_sync(0xffffffff, o, m);
        if (lane8 == 0) out[nb + node] = o + b4S[0];
    }
}

// ============================================================================
extern "C" void kernel_launch(void* const* d_in, const int* in_sizes, int n_in,
                              void* d_out, int out_size) {
    const float* node_vec = (const float*)d_in[0];
    const float* attr     = (const float*)d_in[1];
    const float* W1s      = (const float*)d_in[2];
    const float* b1s      = (const float*)d_in[3];
    // d_in[4..7] = W1g, b1g, W1v1, W1v2 : dead in the reference
    const float* W2       = (const float*)d_in[8];
    const float* b2       = (const float*)d_in[9];
    const float* W3       = (const float*)d_in[10];
    const float* b3       = (const float*)d_in[11];
    const float* W4       = (const float*)d_in[12];
    const float* b4       = (const float*)d_in[13];
    float* out = (float*)d_out;

    const int N = out_size;                    // 8192

    prep_all<<<128, 256>>>(W1s, W2);

    cudaFuncSetAttribute(eq_hmma, cudaFuncAttributeMaxDynamicSharedMemorySize,
                         (int)SMEM_BYTES);
    eq_hmma<<<N / MT, THREADS, SMEM_BYTES>>>(node_vec, attr, b1s, b2, W3, b3, W4, b4, out);
}

// round 17
// speedup vs baseline: 1.0545x; 1.0078x over previous
#include <cuda_runtime.h>
#include <cuda_fp16.h>
#include <cstdint>

// ============================================================================
// Problem constants
// ============================================================================
#define NU 128         // MUL0
#define NV 32          // A
#define KTOT 4096      // NU*NV
#define MT 32          // nodes per block
#define NCHUNK1 32     // stage-1 chunks of K=128
#define NCHUNK2 32     // stage-2 chunks of K=128
#define THREADS 256    // stage1: 4 consumer + 4 producer warps; stage2: all-hands
#define PT 128         // producer thread count

// W1 in fragment-direct layout: flat index (((g64*4+rgrp)*2+nbk)*4+ks)*2+hl, 32 lanes x uint4
__device__ __align__(16) uint4 g_W1F[64 * 4 * 2 * 4 * 2 * 32];   // 2 MB
// W2 in fragment-direct layout: flat index ((g64*2+nbk)*4+ks)*2+hl, 32 lanes x uint4
__device__ __align__(16) uint4 g_W2F[64 * 2 * 4 * 2 * 32];       // 512 KB

// ---- smem layout (bytes) ----
// RING region shared by: stage1 A ring (2 x 16KB), stage2 A ring (2 x 16KB), psum tail
constexpr uint32_t OFF_RING = 1024;       // 65536 bytes
constexpr uint32_t OFF_S    = 66560;      // sT / aT fp32 [128u][33] = 16896
constexpr uint32_t OFF_ATTR = 83456;      // attr fp32 [32n][36] = 4608
constexpr uint32_t OFF_H    = 88064;      // h fp32 [32n][33] = 4224
constexpr uint32_t OFF_W3   = 92288;      // 4096
constexpr uint32_t OFF_B1   = 96384;      // 512
constexpr uint32_t OFF_B2   = 96896;      // 128
constexpr uint32_t OFF_B3   = 97024;      // 128
constexpr uint32_t OFF_W4   = 97152;      // 128
constexpr uint32_t OFF_B4   = 97280;      // 16
constexpr uint32_t SMEM_BYTES = 97296;    // ~95 KB -> 2 CTAs/SM

extern __shared__ char smem_raw[];

__device__ __forceinline__ uint32_t smem_u32(const void* p) {
    uint32_t a;
    asm("{ .reg .u64 t; cvta.to.shared.u64 t, %1; cvt.u32.u64 %0, t; }" : "=r"(a) : "l"(p));
    return a;
}
__device__ __forceinline__ uint32_t swz(uint32_t o) { return o ^ ((o >> 3) & 0x70); }
__device__ __forceinline__ float silu_f(float x) { return x / (1.0f + __expf(-x)); }

#define STS128(r0, r1, r2, r3, sa) \
    asm volatile("st.shared.v4.b32 [%0], {%1, %2, %3, %4};" \
                 :: "r"(sa), "r"(r0), "r"(r1), "r"(r2), "r"(r3) : "memory")

// named barriers: FULL_b = 1+b, EMPTY_b = 3+b, block join = 15 (all count 256)
#define BAR_SYNC_ID(id)   asm volatile("bar.sync %0, %1;"   :: "r"(id), "n"(THREADS) : "memory")
#define BAR_ARRIVE_ID(id) asm volatile("bar.arrive %0, %1;" :: "r"(id), "n"(THREADS) : "memory")
#define BARX() asm volatile("bar.sync 15, %0;" :: "n"(THREADS) : "memory")

__device__ __forceinline__ void ldsm4(uint32_t* r, uint32_t addr) {
    asm volatile("ldmatrix.sync.aligned.m8n8.x4.shared.b16 {%0,%1,%2,%3}, [%4];"
                 : "=r"(r[0]), "=r"(r[1]), "=r"(r[2]), "=r"(r[3]) : "r"(addr));
}
// main pass: fp16 operands, fp32 accumulators
__device__ __forceinline__ void mma_f32(float* c, const uint32_t* a,
                                        uint32_t b0, uint32_t b1) {
    asm volatile(
        "mma.sync.aligned.m16n8k16.row.col.f32.f16.f16.f32 "
        "{%0,%1,%2,%3}, {%4,%5,%6,%7}, {%8,%9}, {%0,%1,%2,%3};"
        : "+f"(c[0]), "+f"(c[1]), "+f"(c[2]), "+f"(c[3])
        : "r"(a[0]), "r"(a[1]), "r"(a[2]), "r"(a[3]), "r"(b0), "r"(b1));
}
// correction passes: fp16 operands, fp16 accumulators
__device__ __forceinline__ void mma_f16(uint32_t* c, const uint32_t* a,
                                        uint32_t b0, uint32_t b1) {
    asm volatile(
        "mma.sync.aligned.m16n8k16.row.col.f16.f16.f16.f16 "
        "{%0,%1}, {%2,%3,%4,%5}, {%6,%7}, {%0,%1};"
        : "+r"(c[0]), "+r"(c[1])
        : "r"(a[0]), "r"(a[1]), "r"(a[2]), "r"(a[3]), "r"(b0), "r"(b1));
}

// ============================================================================
// prep kernel: blocks [0,64) -> W1 fragment layout; blocks [64,128) -> W2 fragment layout
// ============================================================================
__global__ void __launch_bounds__(256) prep_all(const float* __restrict__ W1s,
                                                const float* __restrict__ W2) {
    const int t = threadIdx.x;
    const int b = blockIdx.x;
    if (b < 64) {
        __shared__ float tile[64][132];
        const int g = b;
#pragma unroll
        for (int it = 0; it < 8; ++it) {          // 2048 float4 slots
            int s = it * 256 + t;
            int r = s >> 5, q = s & 31;
            float4 v = *(const float4*)(W1s + (size_t)(g * 64 + r) * NU + q * 4);
            tile[r][q * 4 + 0] = v.x; tile[r][q * 4 + 1] = v.y;
            tile[r][q * 4 + 2] = v.z; tile[r][q * 4 + 3] = v.w;
        }
        __syncthreads();
        const int l = t & 31, s = t >> 5;
        const int hl = s & 1, ks = s >> 1;
#pragma unroll
        for (int rgrp = 0; rgrp < 4; ++rgrp)
#pragma unroll
            for (int nbk = 0; nbk < 2; ++nbk) {
                uint32_t w[4];
#pragma unroll
                for (int j = 0; j < 4; ++j) {
                    int n  = rgrp * 32 + nbk * 16 + ((j >> 1) << 3) + (l >> 2);
                    int kh = ks * 16 + ((j & 1) << 3) + ((l & 3) << 1);
                    float x0 = tile[kh][n]     * 0.125f;
                    float x1 = tile[kh + 1][n] * 0.125f;
                    __half2 h2 = __float22half2_rn(make_float2(x0, x1));
                    float2 hf = __half22float2(h2);
                    __half2 l2 = __float22half2_rn(make_float2(x0 - hf.x, x1 - hf.y));
                    w[j] = hl ? *reinterpret_cast<uint32_t*>(&l2)
                              : *reinterpret_cast<uint32_t*>(&h2);
                }
                size_t flat = ((((size_t)g * 4 + rgrp) * 2 + nbk) * 4 + ks) * 2 + hl;
                g_W1F[flat * 32 + l] = make_uint4(w[0], w[1], w[2], w[3]);
            }
    } else {
        // W2 -> fragment-direct layout (same derivation, n only 32 wide)
        __shared__ float tile[64][36];
        const int g = b - 64;
#pragma unroll
        for (int it = 0; it < 2; ++it) {          // 512 float4 slots
            int s = it * 256 + t;
            int r = s >> 3, q = s & 7;
            float4 v = *(const float4*)(W2 + (size_t)(g * 64 + r) * NV + q * 4);
            tile[r][q * 4 + 0] = v.x; tile[r][q * 4 + 1] = v.y;
            tile[r][q * 4 + 2] = v.z; tile[r][q * 4 + 3] = v.w;
        }
        __syncthreads();
        const int l = t & 31, s = t >> 5;
        const int hl = s & 1, ks = s >> 1;
#pragma unroll
        for (int nbk = 0; nbk < 2; ++nbk) {
            uint32_t w[4];
#pragma unroll
            for (int j = 0; j < 4; ++j) {
                int n  = nbk * 16 + ((j >> 1) << 3) + (l >> 2);
                int kh = ks * 16 + ((j & 1) << 3) + ((l & 3) << 1);
                float x0 = tile[kh][n]     * 0.125f;
                float x1 = tile[kh + 1][n] * 0.125f;
                __half2 h2 = __float22half2_rn(make_float2(x0, x1));
                float2 hf = __half22float2(h2);
                __half2 l2 = __float22half2_rn(make_float2(x0 - hf.x, x1 - hf.y));
                w[j] = hl ? *reinterpret_cast<uint32_t*>(&l2)
                          : *reinterpret_cast<uint32_t*>(&h2);
            }
            size_t flat = (((size_t)g * 2 + nbk) * 4 + ks) * 2 + hl;
            g_W2F[flat * 32 + l] = make_uint4(w[0], w[1], w[2], w[3]);
        }
    }
}

// ============================================================================
// main fused kernel
// ============================================================================
__global__ void __launch_bounds__(THREADS, 2)
eq_hmma(const float* __restrict__ node_vec,   // [N,480]
        const float* __restrict__ attr_g,     // [N,32]
        const float* __restrict__ b1s,        // [128]
        const float* __restrict__ b2,         // [32]
        const float* __restrict__ W3,         // [32,32]
        const float* __restrict__ b3,         // [32]
        const float* __restrict__ W4,         // [32]
        const float* __restrict__ b4,         // [1]
        float* __restrict__ out)              // [N]
{
    const int tid  = threadIdx.x;
    const int wid  = tid >> 5;
    const int lane = tid & 31;
    const int nb   = blockIdx.x * MT;
    const uint32_t sb = smem_u32(smem_raw);
    const bool producer = (wid >= 4);
    const int ptid = tid - 128;

    float* sT    = (float*)(smem_raw + OFF_S);     // [u][33]
    float* attrS = (float*)(smem_raw + OFF_ATTR);  // [n][36]
    float* hS    = (float*)(smem_raw + OFF_H);     // [n][33]
    float* psum  = (float*)(smem_raw + OFF_RING);  // tail reuse: [ksg][32m][32n]
    float* w3S   = (float*)(smem_raw + OFF_W3);
    float* b1S   = (float*)(smem_raw + OFF_B1);
    float* b2S   = (float*)(smem_raw + OFF_B2);
    float* b3S   = (float*)(smem_raw + OFF_B3);
    float* w4S   = (float*)(smem_raw + OFF_W4);
    float* b4S   = (float*)(smem_raw + OFF_B4);

    // stage-1 A ring: buf b (0/1) x sub (0/1) x hi/lo, 4KB each
    auto A1 = [&](int b, int sub, int hl) {
        return sb + OFF_RING + (uint32_t)(b * 16384 + sub * 8192 + hl * 4096);
    };

    // ---- load block inputs (all 256 threads) ----
#pragma unroll
    for (int j = 0; j < 4; ++j) {              // s -> transposed [u][33]
        int i = tid + j * THREADS;             // 1024 float4 slots (32n x 32c4)
        int n = i >> 5, c4 = i & 31;
        float4 v = *(const float4*)(node_vec + (size_t)(nb + n) * 480 + c4 * 4);
        sT[(c4 * 4 + 0) * 33 + n] = v.x;
        sT[(c4 * 4 + 1) * 33 + n] = v.y;
        sT[(c4 * 4 + 2) * 33 + n] = v.z;
        sT[(c4 * 4 + 3) * 33 + n] = v.w;
    }
    {                                          // attr -> [n][36]
        int n = tid >> 3, c4 = tid & 7;
        *(float4*)(attrS + n * 36 + c4 * 4) =
            *(const float4*)(attr_g + (size_t)(nb + n) * NV + c4 * 4);
    }
    ((float4*)w3S)[tid] = ((const float4*)W3)[tid];
    if (tid < 128) b1S[tid] = b1s[tid];
    if (tid < 32) { b2S[tid] = b2[tid]; b3S[tid] = b3[tid]; w4S[tid] = W4[tid]; }
    if (tid == 0) b4S[0] = b4[0];
    __syncthreads();

    // ldmatrix per-lane offsets
    const uint32_t rowA = (uint32_t)((((lane >> 3) & 1) << 3) + (lane & 7));
    const uint32_t colA = (uint32_t)((lane >> 4) << 4);

    // ============================== STAGE 1 (K=128 chunks, R14 verbatim) ==============================
    if (producer) {
        for (int c = 0; c < NCHUNK1; ++c) {
            const int b = c & 1;
            if (c >= 2) BAR_SYNC_ID(3 + b);            // EMPTY
#pragma unroll
            for (int j = 0; j < 4; ++j) {              // sub = j>>1
                const int sub = j >> 1;
                int slot = ptid + (j & 1) * PT;        // 0..255
                int n = slot >> 3, kgs = slot & 7;
                int vbs = (kgs & 3) << 3;
                int u = c * 4 + sub * 2 + (kgs >> 2);
                float su = sT[u * 33 + n] * 0.125f;
                float4 a0 = *(const float4*)(attrS + n * 36 + vbs);
                float4 a1 = *(const float4*)(attrS + n * 36 + vbs + 4);
                float v[8] = {a0.x, a0.y, a0.z, a0.w, a1.x, a1.y, a1.z, a1.w};
                uint32_t hb[4], lb[4];
#pragma unroll
                for (int q = 0; q < 4; ++q) {
                    float x0 = su * v[2 * q], x1 = su * v[2 * q + 1];
                    __half2 h2 = __float22half2_rn(make_float2(x0, x1));
                    float2 hf = __half22float2(h2);
                    __half2 l2 = __float22half2_rn(make_float2(x0 - hf.x, x1 - hf.y));
                    hb[q] = *reinterpret_cast<uint32_t*>(&h2);
                    lb[q] = *reinterpret_cast<uint32_t*>(&l2);
                }
                uint32_t sw = swz((uint32_t)(n * 128 + (kgs << 4)));
                STS128(hb[0], hb[1], hb[2], hb[3], A1(b, sub, 0) + sw);
                STS128(lb[0], lb[1], lb[2], lb[3], A1(b, sub, 1) + sw);
            }
            BAR_ARRIVE_ID(1 + b);                      // FULL (A only)
        }
        BARX();   // consumers wrote aT into sT
    } else {
        // B fragments straight from global (fragment-direct layout)
        auto ldB = [&](uint4* dst, int g64, int ks4) { // dst[nbk*2+hl]
#pragma unroll
            for (int nbk = 0; nbk < 2; ++nbk)
#pragma unroll
                for (int hl = 0; hl < 2; ++hl) {
                    size_t flat = ((((size_t)g64 * 4 + wid) * 2 + nbk) * 4 + ks4) * 2 + hl;
                    dst[nbk * 2 + hl] = __ldg(&g_W1F[flat * 32 + lane]);
                }
        };

        float    accF[2][4][4];
        uint32_t accC[2][4][2];
#pragma unroll
        for (int a = 0; a < 2; ++a)
#pragma unroll
            for (int b = 0; b < 4; ++b) {
#pragma unroll
                for (int q = 0; q < 4; ++q) accF[a][b][q] = 0.0f;
                accC[a][b][0] = 0u; accC[a][b][1] = 0u;
            }

        uint4 bf[2][4];                                // double-buffered per ks step
        ldB(bf[0], 0, 0);                              // t = 0

        for (int c = 0; c < NCHUNK1; ++c) {
            const int b = c & 1;
            BAR_SYNC_ID(1 + b);                        // FULL: A ready
#pragma unroll
            for (int ks8 = 0; ks8 < 8; ++ks8) {
                const int cur = ks8 & 1, nxt = cur ^ 1;
                const int t = c * 8 + ks8;
                if (t + 1 < NCHUNK1 * 8) ldB(bf[nxt], (t + 1) >> 2, (t + 1) & 3);
                const int sub = ks8 >> 2, ks4 = ks8 & 3;
                const uint32_t aHt = A1(b, sub, 0), aLt = A1(b, sub, 1);
                uint32_t aH[2][4], aL[2][4];
#pragma unroll
                for (int mf = 0; mf < 2; ++mf) {
                    uint32_t off = swz((uint32_t)((mf * 16 + rowA) * 128 + ks4 * 32 + colA));
                    ldsm4(aH[mf], aHt + off);
                    ldsm4(aL[mf], aLt + off);
                }
                if (ks8 == 7) BAR_ARRIVE_ID(3 + b);    // EMPTY early (A fully read)
#pragma unroll
                for (int mf = 0; mf < 2; ++mf)
#pragma unroll
                    for (int nf = 0; nf < 4; ++nf) {
                        const int nbk = nf >> 1, p = nf & 1;
                        const uint4 BH = bf[cur][nbk * 2 + 0];
                        const uint4 BL = bf[cur][nbk * 2 + 1];
                        uint32_t h0 = p ? BH.z : BH.x, h1 = p ? BH.w : BH.y;
                        uint32_t l0 = p ? BL.z : BL.x, l1 = p ? BL.w : BL.y;
                        mma_f32(accF[mf][nf], aH[mf], h0, h1);
                        mma_f16(accC[mf][nf], aH[mf], l0, l1);
                        mma_f16(accC[mf][nf], aL[mf], h0, h1);
                    }
            }
        }
        // epilogue 1: silu(c + corr + b1) -> sT[w][node]
        const int n0 = wid * 32;
#pragma unroll
        for (int mf = 0; mf < 2; ++mf)
#pragma unroll
            for (int nf = 0; nf < 4; ++nf) {
                int m = mf * 16 + (lane >> 2);
                int w = n0 + nf * 8 + ((lane & 3) << 1);
                float* cc = accF[mf][nf];
                float2 p0 = __half22float2(*(__half2*)&accC[mf][nf][0]);
                float2 p1 = __half22float2(*(__half2*)&accC[mf][nf][1]);
                sT[w * 33 + m]           = silu_f(cc[0] + p0.x + b1S[w]);
                sT[(w + 1) * 33 + m]     = silu_f(cc[1] + p0.y + b1S[w + 1]);
                sT[w * 33 + m + 8]       = silu_f(cc[2] + p1.x + b1S[w]);
                sT[(w + 1) * 33 + m + 8] = silu_f(cc[3] + p1.y + b1S[w + 1]);
            }
        BARX();   // join with producers; sT (aT) ready
    }

    // ========== STAGE 2: all-hands, K=128 chunks, A-only ring, B from L2 ==========
    {
        const int n2  = tid >> 3, kg2 = tid & 7;
        const int u2d = kg2 >> 2, vb2 = (kg2 & 3) << 3;
        float attrR[8];
#pragma unroll
        for (int q = 0; q < 8; ++q) attrR[q] = attrS[n2 * 36 + vb2 + q];
        const uint32_t swA2 = swz((uint32_t)(n2 * 128 + (kg2 << 4)));

        // buf b (0/1) x sub (0/1) x hi/lo, 4KB each (A only)
        auto A2 = [&](int b, int s, int hl) {
            return sb + OFF_RING + (uint32_t)(b * 16384 + s * 8192 + hl * 4096);
        };

        auto fill2 = [&](int c, int b) {
#pragma unroll
            for (int s = 0; s < 2; ++s) {
                float su = sT[(c * 4 + s * 2 + u2d) * 33 + n2] * 0.125f;
                uint32_t hb[4], lb[4];
#pragma unroll
                for (int q = 0; q < 4; ++q) {
                    float x0 = su * attrR[2 * q], x1 = su * attrR[2 * q + 1];
                    __half2 h2 = __float22half2_rn(make_float2(x0, x1));
                    float2 hf = __half22float2(h2);
                    __half2 l2 = __float22half2_rn(make_float2(x0 - hf.x, x1 - hf.y));
                    hb[q] = *reinterpret_cast<uint32_t*>(&h2);
                    lb[q] = *reinterpret_cast<uint32_t*>(&l2);
                }
                STS128(hb[0], hb[1], hb[2], hb[3], A2(b, s, 0) + swA2);
                STS128(lb[0], lb[1], lb[2], lb[3], A2(b, s, 1) + swA2);
            }
        };

        const int mg  = wid >> 2;            // 0..1 (m half)
        const int ksg = wid & 3;             // 0..3 (k slice of 16)

        // B fragments straight from global (warp's ksg slice only)
        auto ldB2 = [&](uint4* dst, int g64) {         // dst[nbk*2+hl]
#pragma unroll
            for (int nbk = 0; nbk < 2; ++nbk)
#pragma unroll
                for (int hl = 0; hl < 2; ++hl) {
                    size_t flat = (((size_t)g64 * 2 + nbk) * 4 + ksg) * 2 + hl;
                    dst[nbk * 2 + hl] = __ldg(&g_W2F[flat * 32 + lane]);
                }
        };

        float    accF[4][4];
        uint32_t accC[4][2];
#pragma unroll
        for (int b = 0; b < 4; ++b) {
#pragma unroll
            for (int q = 0; q < 4; ++q) accF[b][q] = 0.0f;
            accC[b][0] = 0u; accC[b][1] = 0u;
        }

        uint4 bf[2][4];
        ldB2(bf[0], 0);                      // t = 0
        fill2(0, 0);

        for (int c = 0; c < NCHUNK2; ++c) {
            const int b = c & 1;
            __syncthreads();                 // publishes fill of buf b; retires reads of b^1
            if (c + 1 < NCHUNK2) fill2(c + 1, b ^ 1);
#pragma unroll
            for (int s = 0; s < 2; ++s) {
                const int cur = (c * 2 + s) & 1, nxt = cur ^ 1;
                const int t = c * 2 + s;
                if (t + 1 < NCHUNK2 * 2) ldB2(bf[nxt], t + 1);
                uint32_t aH[4], aL[4];
                uint32_t off = swz((uint32_t)((mg * 16 + rowA) * 128 + ksg * 32 + colA));
                ldsm4(aH, A2(b, s, 0) + off);
                ldsm4(aL, A2(b, s, 1) + off);
#pragma unroll
                for (int nf = 0; nf < 4; ++nf) {
                    const int nbk = nf >> 1, p = nf & 1;
                    const uint4 BH = bf[cur][nbk * 2 + 0];
                    const uint4 BL = bf[cur][nbk * 2 + 1];
                    uint32_t h0 = p ? BH.z : BH.x, h1 = p ? BH.w : BH.y;
                    uint32_t l0 = p ? BL.z : BL.x, l1 = p ? BL.w : BL.y;
                    mma_f32(accF[nf], aH, h0, h1);
                    mma_f16(accC[nf], aH, l0, l1);
                    mma_f16(accC[nf], aL, h0, h1);
                }
            }
        }
        __syncthreads();   // ring buffers dead; region free for psum

        // write k-partials (main + corrections) to psum
#pragma unroll
        for (int nf = 0; nf < 4; ++nf) {
            int m = mg * 16 + (lane >> 2);
            int w = nf * 8 + ((lane & 3) << 1);
            float* cc = accF[nf];
            float2 p0 = __half22float2(*(__half2*)&accC[nf][0]);
            float2 p1 = __half22float2(*(__half2*)&accC[nf][1]);
            psum[(ksg * 32 + m) * 32 + w]         = cc[0] + p0.x;
            psum[(ksg * 32 + m) * 32 + w + 1]     = cc[1] + p0.y;
            psum[(ksg * 32 + m + 8) * 32 + w]     = cc[2] + p1.x;
            psum[(ksg * 32 + m + 8) * 32 + w + 1] = cc[3] + p1.y;
        }
        __syncthreads();
    }

    // reduce 4 k-partials + bias -> hS (all 256 threads)
#pragma unroll
    for (int j = 0; j < 4; ++j) {
        int idx = tid + j * THREADS;           // [0, 1024)
        int m = idx >> 5, n = idx & 31;
        float h = psum[m * 32 + n] + psum[(32 + m) * 32 + n]
                + psum[(64 + m) * 32 + n] + psum[(96 + m) * 32 + n] + b2S[n];
        hS[m * 33 + n] = h;
    }
    __syncthreads();

    // ======================= stage 3/4: 8 threads per node =======================
    {
        const int node  = tid >> 3;            // [0,32)
        const int lane8 = tid & 7;
        const float inv32 = 0.17677669529663687f;  // 1/sqrt(32)
        float o = 0.0f;
#pragma unroll
        for (int j = 0; j < 4; ++j) {
            int w = lane8 + j * 8;
            float z = 0.0f;
#pragma unroll
            for (int k = 0; k < 32; ++k) z += hS[node * 33 + k] * w3S[k * 32 + w];
            z = z * inv32 + b3S[w];
            o += silu_f(z) * (w4S[w] * inv32);
        }
#pragma unroll
        for (int m = 1; m < 8; m <<= 1)
            o += __shfl_xor_sync(0xffffffff, o, m);
        if (lane8 == 0) out[nb + node] = o + b4S[0];
    }
}

// ============================================================================
extern "C" void kernel_launch(void* const* d_in, const int* in_sizes, int n_in,
                              void* d_out, int out_size) {
    const float* node_vec = (const float*)d_in[0];
    const float* attr     = (const float*)d_in[1];
    const float* W1s      = (const float*)d_in[2];
    const float* b1s      = (const float*)d_in[3];
    // d_in[4..7] = W1g, b1g, W1v1, W1v2 : dead in the reference
    const float* W2       = (const float*)d_in[8];
    const float* b2       = (const float*)d_in[9];
    const float* W3       = (const float*)d_in[10];
    const float* b3       = (const float*)d_in[11];
    const float* W4       = (const float*)d_in[12];
    const float* b4       = (const float*)d_in[13];
    float* out = (float*)d_out;

    const int N = out_size;                    // 8192

    prep_all<<<128, 256>>>(W1s, W2);

    cudaFuncSetAttribute(eq_hmma, cudaFuncAttributeMaxDynamicSharedMemorySize,
                         (int)SMEM_BYTES);
    eq_hmma<<<N / MT, THREADS, SMEM_BYTES>>>(node_vec, attr, b1s, b2, W3, b3, W4, b4, out);
}